// round 1
// baseline (speedup 1.0000x reference)
#include <cuda_runtime.h>
#include <cuda_bf16.h>
#include <stdint.h>

// Problem constants (fixed by the dataset)
static constexpr int IN_DIM   = 4096;
static constexpr int OUT_DIM  = 4096;
static constexpr int N_TOKENS = 8192;
static constexpr int RANK     = 16;
// ALPHA / RANK = 32 / 16 = 2.0
static constexpr float LORA_SCALE = 2.0f;

// NF4 codebook
__constant__ float c_nf4[16] = {
    -1.0f, -0.6961928009986877f, -0.5250730514526367f, -0.39491748809814453f,
    -0.28444138169288635f, -0.18477343022823334f, -0.09105003625154495f, 0.0f,
    0.07958029955625534f, 0.16093020141124725f, 0.24611230194568634f,
    0.33791524171829224f, 0.44070982933044434f, 0.5626170039176941f,
    0.7229568362236023f, 1.0f};

// Scratch: effective weight W_eff[o][i] = dequant + 2 * (B@A)[o][i]
// 4096*4096 floats = 64 MB, static device array (no runtime allocation).
__device__ float g_weff[OUT_DIM * IN_DIM];

// ---------------------------------------------------------------------------
// Kernel 1: NF4 dequant + LoRA fold.
// idx = o * IN_DIM + i, one element per thread. codes are flat in the same
// order as w.reshape(-1, 64): block = idx >> 6.
// ---------------------------------------------------------------------------
__global__ __launch_bounds__(256) void dequant_fold_kernel(
    const int*   __restrict__ codes,
    const float* __restrict__ scalers,
    const float* __restrict__ Aw,   // [RANK, IN_DIM]
    const float* __restrict__ Bw)   // [OUT_DIM, RANK]
{
    int idx = blockIdx.x * blockDim.x + threadIdx.x;
    if (idx >= OUT_DIM * IN_DIM) return;
    int o = idx >> 12;          // / IN_DIM
    int i = idx & (IN_DIM - 1);

    float w = c_nf4[codes[idx]] * scalers[idx >> 6];

    float acc = 0.0f;
#pragma unroll
    for (int r = 0; r < RANK; r++) {
        acc = fmaf(Bw[(o << 4) + r], Aw[(r << 12) + i], acc);
    }
    g_weff[idx] = fmaf(LORA_SCALE, acc, w);
}

// ---------------------------------------------------------------------------
// Kernel 2: C[M,N] = A[M,K] * B[N,K]^T   (B = g_weff, row-major over [N,K])
// 128x128 tile, BK=16, 256 threads, 8x8 per-thread micro-tile.
// ---------------------------------------------------------------------------
static constexpr int GM = N_TOKENS;  // 8192
static constexpr int GN = OUT_DIM;   // 4096
static constexpr int GK = IN_DIM;    // 4096
static constexpr int BM = 128;
static constexpr int BN = 128;
static constexpr int BK = 16;

__global__ __launch_bounds__(256) void gemm_kernel(
    const float* __restrict__ A,   // [GM, GK]
    float*       __restrict__ C)   // [GM, GN]
{
    const float* __restrict__ B = g_weff;   // [GN, GK]

    __shared__ float As[BK][BM];
    __shared__ float Bs[BK][BN];

    const int tid  = threadIdx.x;
    const int brow = blockIdx.y * BM;   // M offset
    const int bcol = blockIdx.x * BN;   // N offset

    const int tx = tid & 15;            // 0..15 -> N direction
    const int ty = tid >> 4;            // 0..15 -> M direction

    // Loader mapping: 512 float4s per tile (128 rows x 4 quads), 2 per thread.
    const int f0  = tid * 2;
    const int r0  = f0 >> 2;
    const int q0  = (f0 & 3) * 4;
    const int f1  = f0 + 1;
    const int r1  = f1 >> 2;
    const int q1  = (f1 & 3) * 4;

    float acc[8][8];
#pragma unroll
    for (int i = 0; i < 8; i++)
#pragma unroll
        for (int j = 0; j < 8; j++) acc[i][j] = 0.0f;

    const float* Abase0 = A + (size_t)(brow + r0) * GK + q0;
    const float* Abase1 = A + (size_t)(brow + r1) * GK + q1;
    const float* Bbase0 = B + (size_t)(bcol + r0) * GK + q0;
    const float* Bbase1 = B + (size_t)(bcol + r1) * GK + q1;

    for (int kb = 0; kb < GK; kb += BK) {
        float4 a0 = *(const float4*)(Abase0 + kb);
        float4 a1 = *(const float4*)(Abase1 + kb);
        float4 b0 = *(const float4*)(Bbase0 + kb);
        float4 b1 = *(const float4*)(Bbase1 + kb);

        As[q0 + 0][r0] = a0.x; As[q0 + 1][r0] = a0.y;
        As[q0 + 2][r0] = a0.z; As[q0 + 3][r0] = a0.w;
        As[q1 + 0][r1] = a1.x; As[q1 + 1][r1] = a1.y;
        As[q1 + 2][r1] = a1.z; As[q1 + 3][r1] = a1.w;

        Bs[q0 + 0][r0] = b0.x; Bs[q0 + 1][r0] = b0.y;
        Bs[q0 + 2][r0] = b0.z; Bs[q0 + 3][r0] = b0.w;
        Bs[q1 + 0][r1] = b1.x; Bs[q1 + 1][r1] = b1.y;
        Bs[q1 + 2][r1] = b1.z; Bs[q1 + 3][r1] = b1.w;

        __syncthreads();

#pragma unroll
        for (int kk = 0; kk < BK; kk++) {
            float a[8], b[8];
            *(float4*)&a[0] = *(const float4*)&As[kk][ty * 8 + 0];
            *(float4*)&a[4] = *(const float4*)&As[kk][ty * 8 + 4];
            *(float4*)&b[0] = *(const float4*)&Bs[kk][tx * 8 + 0];
            *(float4*)&b[4] = *(const float4*)&Bs[kk][tx * 8 + 4];
#pragma unroll
            for (int i = 0; i < 8; i++)
#pragma unroll
                for (int j = 0; j < 8; j++)
                    acc[i][j] = fmaf(a[i], b[j], acc[i][j]);
        }
        __syncthreads();
    }

    // Store 8x8 micro-tile
#pragma unroll
    for (int i = 0; i < 8; i++) {
        const int row = brow + ty * 8 + i;
        float* crow = C + (size_t)row * GN + bcol + tx * 8;
        float4 v0 = make_float4(acc[i][0], acc[i][1], acc[i][2], acc[i][3]);
        float4 v1 = make_float4(acc[i][4], acc[i][5], acc[i][6], acc[i][7]);
        *(float4*)(crow + 0) = v0;
        *(float4*)(crow + 4) = v1;
    }
}

// ---------------------------------------------------------------------------
// Launch
// Inputs (metadata order): x [8192*4096] f32, codes [262144*64] i32,
// scalers [262144] f32, lora_a_w [16*4096] f32, lora_b_w [4096*16] f32.
// Output: float32 [8192*4096].
// ---------------------------------------------------------------------------
extern "C" void kernel_launch(void* const* d_in, const int* in_sizes, int n_in,
                              void* d_out, int out_size)
{
    const float* x       = (const float*)d_in[0];
    const int*   codes   = (const int*)  d_in[1];
    const float* scalers = (const float*)d_in[2];
    const float* Aw      = (const float*)d_in[3];
    const float* Bw      = (const float*)d_in[4];
    float*       out     = (float*)d_out;

    // 1) Build effective weight (dequant + LoRA fold)
    {
        int total = OUT_DIM * IN_DIM;
        int threads = 256;
        int blocks = (total + threads - 1) / threads;
        dequant_fold_kernel<<<blocks, threads>>>(codes, scalers, Aw, Bw);
    }

    // 2) GEMM: out = x @ W_eff^T
    {
        dim3 grid(GN / BN, GM / BM);   // (32, 64)
        gemm_kernel<<<grid, 256>>>(x, out);
    }
}

// round 3
// speedup vs baseline: 4.0026x; 4.0026x over previous
#include <cuda_runtime.h>
#include <cuda_bf16.h>
#include <stdint.h>

// ---------------------------------------------------------------------------
// Problem constants
// ---------------------------------------------------------------------------
static constexpr int IN_DIM   = 4096;   // K
static constexpr int OUT_DIM  = 4096;   // N
static constexpr int N_TOKENS = 8192;   // M
static constexpr int RANK     = 16;
static constexpr float LORA_SCALE = 2.0f;   // ALPHA / RANK

static constexpr int BM = 128;
static constexpr int BN = 128;
static constexpr int BK = 32;                     // floats
static constexpr int NIT = IN_DIM / BK;           // 128
static constexpr int A_TILE = BM * BK * 4;        // 16 KB
static constexpr int B_TILE = BN * BK * 4;        // 16 KB
static constexpr int STAGE  = A_TILE + B_TILE;    // 32 KB
static constexpr int SMEM_DYN = 2 * STAGE;        // 64 KB

// NF4 codebook
__constant__ float c_nf4[16] = {
    -1.0f, -0.6961928009986877f, -0.5250730514526367f, -0.39491748809814453f,
    -0.28444138169288635f, -0.18477343022823334f, -0.09105003625154495f, 0.0f,
    0.07958029955625534f, 0.16093020141124725f, 0.24611230194568634f,
    0.33791524171829224f, 0.44070982933044434f, 0.5626170039176941f,
    0.7229568362236023f, 1.0f};

// Effective weight scratch (dequant + LoRA fold): 64 MB static device array.
__device__ float g_weff[OUT_DIM * IN_DIM];

// ---------------------------------------------------------------------------
// Kernel 1: NF4 dequant + LoRA fold (4 elements / thread)
// ---------------------------------------------------------------------------
__global__ __launch_bounds__(256) void dequant_fold_kernel(
    const int4*  __restrict__ codes4,
    const float* __restrict__ scalers,
    const float* __restrict__ Aw,   // [RANK, IN_DIM]
    const float* __restrict__ Bw)   // [OUT_DIM, RANK]
{
    int idx4 = blockIdx.x * 256 + threadIdx.x;
    int base = idx4 * 4;
    int o = base >> 12;                 // / IN_DIM
    int i = base & (IN_DIM - 1);

    int4 c = codes4[idx4];
    float sc = scalers[base >> 6];

    float4 w;
    w.x = c_nf4[c.x] * sc;
    w.y = c_nf4[c.y] * sc;
    w.z = c_nf4[c.z] * sc;
    w.w = c_nf4[c.w] * sc;

    float4 acc = make_float4(0.f, 0.f, 0.f, 0.f);
    const float* bw = Bw + (o << 4);
#pragma unroll
    for (int r = 0; r < RANK; r++) {
        float b = bw[r];
        float4 a = *(const float4*)(Aw + (r << 12) + i);
        acc.x = fmaf(b, a.x, acc.x);
        acc.y = fmaf(b, a.y, acc.y);
        acc.z = fmaf(b, a.z, acc.z);
        acc.w = fmaf(b, a.w, acc.w);
    }
    float4 out;
    out.x = fmaf(LORA_SCALE, acc.x, w.x);
    out.y = fmaf(LORA_SCALE, acc.y, w.y);
    out.z = fmaf(LORA_SCALE, acc.z, w.z);
    out.w = fmaf(LORA_SCALE, acc.w, w.w);
    *(float4*)(g_weff + base) = out;
}

// ---------------------------------------------------------------------------
// Helpers
// ---------------------------------------------------------------------------
__device__ __forceinline__ uint32_t smem_u32(const void* p) {
    uint32_t a;
    asm("{ .reg .u64 t; cvta.to.shared.u64 t, %1; cvt.u32.u64 %0, t; }"
        : "=r"(a) : "l"(p));
    return a;
}

__device__ __forceinline__ void cp_async16(uint32_t dst, const void* src) {
    asm volatile("cp.async.cg.shared.global [%0], [%1], 16;"
                 :: "r"(dst), "l"(src));
}
__device__ __forceinline__ void cp_commit() {
    asm volatile("cp.async.commit_group;" ::: "memory");
}
__device__ __forceinline__ void cp_wait1() {
    asm volatile("cp.async.wait_group 1;" ::: "memory");
}
__device__ __forceinline__ void cp_wait0() {
    asm volatile("cp.async.wait_group 0;" ::: "memory");
}

__device__ __forceinline__ uint32_t f2tf32(float f) {
    uint32_t r;
    asm("cvt.rna.tf32.f32 %0, %1;" : "=r"(r) : "f"(f));
    return r;
}

// row-major tile with 128B rows; 16B chunks XOR-swizzled by (row & 7)
__device__ __forceinline__ int swz(int row, int chunk) {
    return row * 128 + ((chunk ^ (row & 7)) << 4);
}

__device__ __forceinline__ void mma_tf32(
    float& c0, float& c1, float& c2, float& c3,
    uint32_t a0, uint32_t a1, uint32_t a2, uint32_t a3,
    uint32_t b0, uint32_t b1)
{
    asm volatile(
        "mma.sync.aligned.m16n8k8.row.col.f32.tf32.tf32.f32 "
        "{%0,%1,%2,%3}, {%4,%5,%6,%7}, {%8,%9}, {%0,%1,%2,%3};"
        : "+f"(c0), "+f"(c1), "+f"(c2), "+f"(c3)
        : "r"(a0), "r"(a1), "r"(a2), "r"(a3), "r"(b0), "r"(b1));
}

// ---------------------------------------------------------------------------
// Kernel 2: tf32 mma.sync GEMM  C[M,N] = A[M,K] * B[N,K]^T  (B = g_weff)
// CTA 128x128, 8 warps (2 m x 4 n), warp tile 64x32, BK=32, double buffer.
// ---------------------------------------------------------------------------
__global__ __launch_bounds__(256, 2)
void gemm_tf32_kernel(const float* __restrict__ A, float* __restrict__ C)
{
    extern __shared__ char dynb[];
    const uint32_t sbase = smem_u32(dynb);

    const int tid   = threadIdx.x;
    const int wid   = tid >> 5;
    const int lane  = tid & 31;
    const int warpm = wid & 1;          // 0..1
    const int warpn = wid >> 1;         // 0..3
    const int lr    = lane >> 2;        // 0..7
    const int lk    = lane & 3;         // 0..3

    const int brow = blockIdx.y * BM;
    const int bcol = blockIdx.x * BN;

    const float* __restrict__ Bg = g_weff;
    const float* Agb = A  + (size_t)brow * IN_DIM;
    const float* Bgb = Bg + (size_t)bcol * IN_DIM;

    // loader mapping: per matrix 1024 16B-chunks; 256 threads x 4
    // idx = t + i*256 ; row = idx>>3 (0..127), q = idx&7
    auto load_tile = [&](int buf, int kb) {
        const uint32_t sA = sbase + buf * STAGE;
        const uint32_t sB = sA + A_TILE;
#pragma unroll
        for (int i = 0; i < 4; i++) {
            int idx = tid + i * 256;
            int row = idx >> 3;
            int q   = idx & 7;
            cp_async16(sA + swz(row, q), Agb + (size_t)row * IN_DIM + kb + q * 4);
        }
#pragma unroll
        for (int i = 0; i < 4; i++) {
            int idx = tid + i * 256;
            int row = idx >> 3;
            int q   = idx & 7;
            cp_async16(sB + swz(row, q), Bgb + (size_t)row * IN_DIM + kb + q * 4);
        }
    };

    float acc[4][4][4];
#pragma unroll
    for (int mt = 0; mt < 4; mt++)
#pragma unroll
        for (int nt = 0; nt < 4; nt++)
#pragma unroll
            for (int r = 0; r < 4; r++) acc[mt][nt][r] = 0.0f;

    load_tile(0, 0);  cp_commit();
    load_tile(1, BK); cp_commit();

    for (int it = 0; it < NIT; ++it) {
        cp_wait1();
        __syncthreads();
        const int buf = it & 1;
        const char* sA = dynb + buf * STAGE;
        const char* sB = sA + A_TILE;

#pragma unroll
        for (int ks = 0; ks < 4; ks++) {
            // A fragments: 4 m-tiles
            uint32_t af[4][4];
#pragma unroll
            for (int mt = 0; mt < 4; mt++) {
                const int m0 = warpm * 64 + mt * 16 + lr;
                const int c0 = 2 * ks;
                const float* p0 = (const float*)(sA + swz(m0,     c0)     + lk * 4);
                const float* p2 = (const float*)(sA + swz(m0,     c0 + 1) + lk * 4);
                const float* p1 = (const float*)(sA + swz(m0 + 8, c0)     + lk * 4);
                const float* p3 = (const float*)(sA + swz(m0 + 8, c0 + 1) + lk * 4);
                af[mt][0] = f2tf32(*p0);
                af[mt][1] = f2tf32(*p1);
                af[mt][2] = f2tf32(*p2);
                af[mt][3] = f2tf32(*p3);
            }
            // B fragments: 4 n-tiles
            uint32_t bf[4][2];
#pragma unroll
            for (int nt = 0; nt < 4; nt++) {
                const int n0 = warpn * 32 + nt * 8 + lr;
                const int c0 = 2 * ks;
                const float* q0 = (const float*)(sB + swz(n0, c0)     + lk * 4);
                const float* q1 = (const float*)(sB + swz(n0, c0 + 1) + lk * 4);
                bf[nt][0] = f2tf32(*q0);
                bf[nt][1] = f2tf32(*q1);
            }
#pragma unroll
            for (int mt = 0; mt < 4; mt++)
#pragma unroll
                for (int nt = 0; nt < 4; nt++)
                    mma_tf32(acc[mt][nt][0], acc[mt][nt][1],
                             acc[mt][nt][2], acc[mt][nt][3],
                             af[mt][0], af[mt][1], af[mt][2], af[mt][3],
                             bf[nt][0], bf[nt][1]);
        }

        __syncthreads();
        if (it + 2 < NIT) load_tile(buf, (it + 2) * BK);
        cp_commit();
    }

    // Epilogue: each thread owns, per (mt,nt): rows m+lr (+8), cols n+2*lk(+1)
#pragma unroll
    for (int mt = 0; mt < 4; mt++) {
        const int r0 = brow + warpm * 64 + mt * 16 + lr;
#pragma unroll
        for (int nt = 0; nt < 4; nt++) {
            const int ccol = bcol + warpn * 32 + nt * 8 + 2 * lk;
            float2 v0 = make_float2(acc[mt][nt][0], acc[mt][nt][1]);
            float2 v1 = make_float2(acc[mt][nt][2], acc[mt][nt][3]);
            *(float2*)(C + (size_t)r0       * OUT_DIM + ccol) = v0;
            *(float2*)(C + (size_t)(r0 + 8) * OUT_DIM + ccol) = v1;
        }
    }
}

// ---------------------------------------------------------------------------
// Launch
// ---------------------------------------------------------------------------
extern "C" void kernel_launch(void* const* d_in, const int* in_sizes, int n_in,
                              void* d_out, int out_size)
{
    const float* x       = (const float*)d_in[0];
    const int4*  codes   = (const int4*) d_in[1];
    const float* scalers = (const float*)d_in[2];
    const float* Aw      = (const float*)d_in[3];
    const float* Bw      = (const float*)d_in[4];
    float*       out     = (float*)d_out;

    // 1) effective weight (dequant + LoRA fold)
    {
        int blocks = (OUT_DIM * IN_DIM / 4) / 256;   // 16384
        dequant_fold_kernel<<<blocks, 256>>>(codes, scalers, Aw, Bw);
    }

    // 2) tf32 mma.sync GEMM: out = x @ W_eff^T
    {
        static bool attr_set = false;
        if (!attr_set) {
            cudaFuncSetAttribute(gemm_tf32_kernel,
                                 cudaFuncAttributeMaxDynamicSharedMemorySize, SMEM_DYN);
            attr_set = true;
        }
        dim3 grid(OUT_DIM / BN, N_TOKENS / BM);   // (32, 64)
        gemm_tf32_kernel<<<grid, 256, SMEM_DYN>>>(x, out);
    }
}

// round 4
// speedup vs baseline: 7.1540x; 1.7873x over previous
#include <cuda_runtime.h>
#include <cuda_fp16.h>
#include <stdint.h>

// ---------------------------------------------------------------------------
// Problem constants
// ---------------------------------------------------------------------------
static constexpr int IN_DIM   = 4096;   // K
static constexpr int OUT_DIM  = 4096;   // N
static constexpr int N_TOKENS = 8192;   // M
static constexpr int RANK     = 16;
static constexpr float LORA_SCALE = 2.0f;   // ALPHA / RANK

// GEMM tiling: CTA 256x128, 16 warps (4m x 4n), warp tile 64x32, BK=32 halves.
static constexpr int BM = 256;
static constexpr int BN = 128;
static constexpr int BK = 32;                       // halves (64 B rows)
static constexpr int NIT = IN_DIM / BK;             // 128
static constexpr int A_TILE = BM * BK * 2;          // 16 KB
static constexpr int B_TILE = BN * BK * 2;          // 8 KB
static constexpr int STAGE  = A_TILE + B_TILE;      // 24 KB
static constexpr int NSTAGE = 4;
static constexpr int SMEM_DYN = NSTAGE * STAGE;     // 96 KB

// NF4 codebook
__constant__ float c_nf4[16] = {
    -1.0f, -0.6961928009986877f, -0.5250730514526367f, -0.39491748809814453f,
    -0.28444138169288635f, -0.18477343022823334f, -0.09105003625154495f, 0.0f,
    0.07958029955625534f, 0.16093020141124725f, 0.24611230194568634f,
    0.33791524171829224f, 0.44070982933044434f, 0.5626170039176941f,
    0.7229568362236023f, 1.0f};

// fp16 scratch: W_eff (32 MB) and x (64 MB)
__device__ __half g_weffh[(size_t)OUT_DIM * IN_DIM];
__device__ __half g_xh[(size_t)N_TOKENS * IN_DIM];

// ---------------------------------------------------------------------------
// Helpers
// ---------------------------------------------------------------------------
__device__ __forceinline__ uint32_t smem_u32(const void* p) {
    uint32_t a;
    asm("{ .reg .u64 t; cvta.to.shared.u64 t, %1; cvt.u32.u64 %0, t; }"
        : "=r"(a) : "l"(p));
    return a;
}
__device__ __forceinline__ void cp_async16(uint32_t dst, const void* src) {
    asm volatile("cp.async.cg.shared.global [%0], [%1], 16;" :: "r"(dst), "l"(src));
}
__device__ __forceinline__ void cp_commit() {
    asm volatile("cp.async.commit_group;" ::: "memory");
}
template <int N>
__device__ __forceinline__ void cp_wait() {
    asm volatile("cp.async.wait_group %0;" :: "n"(N) : "memory");
}
__device__ __forceinline__ void ldmatrix_x4(uint32_t& r0, uint32_t& r1,
                                            uint32_t& r2, uint32_t& r3,
                                            uint32_t addr) {
    asm volatile("ldmatrix.sync.aligned.m8n8.x4.shared.b16 {%0,%1,%2,%3}, [%4];"
                 : "=r"(r0), "=r"(r1), "=r"(r2), "=r"(r3) : "r"(addr));
}
__device__ __forceinline__ void mma_f16(
    float& c0, float& c1, float& c2, float& c3,
    uint32_t a0, uint32_t a1, uint32_t a2, uint32_t a3,
    uint32_t b0, uint32_t b1)
{
    asm volatile(
        "mma.sync.aligned.m16n8k16.row.col.f32.f16.f16.f32 "
        "{%0,%1,%2,%3}, {%4,%5,%6,%7}, {%8,%9}, {%0,%1,%2,%3};"
        : "+f"(c0), "+f"(c1), "+f"(c2), "+f"(c3)
        : "r"(a0), "r"(a1), "r"(a2), "r"(a3), "r"(b0), "r"(b1));
}

// smem tile: row-major, 64 B rows, 4 chunks of 16 B, XOR-swizzled.
// swizzle: chunk ^= (row>>1)&3  -> conflict-free for ldmatrix 8-row groups.
__device__ __forceinline__ uint32_t swz(int row, int chunk) {
    return (uint32_t)(row * 64 + ((chunk ^ ((row >> 1) & 3)) << 4));
}

// ---------------------------------------------------------------------------
// Kernel 1: NF4 dequant + LoRA fold -> fp16 W_eff (4 elements / thread)
// ---------------------------------------------------------------------------
__global__ __launch_bounds__(256) void dequant_fold_kernel(
    const int4*  __restrict__ codes4,
    const float* __restrict__ scalers,
    const float* __restrict__ Aw,   // [RANK, IN_DIM]
    const float* __restrict__ Bw)   // [OUT_DIM, RANK]
{
    int idx4 = blockIdx.x * 256 + threadIdx.x;
    int base = idx4 * 4;
    int o = base >> 12;
    int i = base & (IN_DIM - 1);

    int4 c = codes4[idx4];
    float sc = scalers[base >> 6];

    float4 w;
    w.x = c_nf4[c.x] * sc;
    w.y = c_nf4[c.y] * sc;
    w.z = c_nf4[c.z] * sc;
    w.w = c_nf4[c.w] * sc;

    float4 acc = make_float4(0.f, 0.f, 0.f, 0.f);
    const float* bw = Bw + (o << 4);
#pragma unroll
    for (int r = 0; r < RANK; r++) {
        float b = bw[r];
        float4 a = *(const float4*)(Aw + (r << 12) + i);
        acc.x = fmaf(b, a.x, acc.x);
        acc.y = fmaf(b, a.y, acc.y);
        acc.z = fmaf(b, a.z, acc.z);
        acc.w = fmaf(b, a.w, acc.w);
    }
    __half2 h0 = __floats2half2_rn(fmaf(LORA_SCALE, acc.x, w.x),
                                   fmaf(LORA_SCALE, acc.y, w.y));
    __half2 h1 = __floats2half2_rn(fmaf(LORA_SCALE, acc.z, w.z),
                                   fmaf(LORA_SCALE, acc.w, w.w));
    uint2 packed;
    packed.x = *(uint32_t*)&h0;
    packed.y = *(uint32_t*)&h1;
    *(uint2*)(g_weffh + base) = packed;
}

// ---------------------------------------------------------------------------
// Kernel 1b: x -> fp16 (8 elements / thread)
// ---------------------------------------------------------------------------
__global__ __launch_bounds__(256) void x_to_half_kernel(const float4* __restrict__ x4)
{
    int idx = blockIdx.x * 256 + threadIdx.x;    // one per 8 elements
    float4 v0 = x4[idx * 2 + 0];
    float4 v1 = x4[idx * 2 + 1];
    __half2 h0 = __floats2half2_rn(v0.x, v0.y);
    __half2 h1 = __floats2half2_rn(v0.z, v0.w);
    __half2 h2 = __floats2half2_rn(v1.x, v1.y);
    __half2 h3 = __floats2half2_rn(v1.z, v1.w);
    uint4 packed;
    packed.x = *(uint32_t*)&h0;
    packed.y = *(uint32_t*)&h1;
    packed.z = *(uint32_t*)&h2;
    packed.w = *(uint32_t*)&h3;
    *(uint4*)(g_xh + (size_t)idx * 8) = packed;
}

// ---------------------------------------------------------------------------
// Kernel 2: fp16 mma.sync GEMM  C[M,N] = A[M,K] * B[N,K]^T
// A = g_xh, B = g_weffh. 512 threads, 4-stage cp.async pipeline.
// ---------------------------------------------------------------------------
__global__ __launch_bounds__(512, 1)
void gemm_f16_kernel(float* __restrict__ C)
{
    extern __shared__ char dynb[];
    const uint32_t sbase = smem_u32(dynb);

    const int tid   = threadIdx.x;
    const int wid   = tid >> 5;
    const int lane  = tid & 31;
    const int warpm = wid & 3;           // 0..3 -> m offset *64
    const int warpn = wid >> 2;          // 0..3 -> n offset *32

    const int brow = blockIdx.y * BM;
    const int bcol = blockIdx.x * BN;

    const __half* Agb = g_xh    + (size_t)brow * IN_DIM;
    const __half* Bgb = g_weffh + (size_t)bcol * IN_DIM;

    // --- stage loader: A 1024 chunks (2/thread), B 512 chunks (1/thread) ---
    auto load_stage = [&](int stage, int kb) {
        const uint32_t sA = sbase + stage * STAGE;
        const uint32_t sB = sA + A_TILE;
#pragma unroll
        for (int i = 0; i < 2; i++) {
            int idx = tid + i * 512;
            int row = idx >> 2;            // 0..255
            int ch  = idx & 3;
            cp_async16(sA + swz(row, ch), Agb + (size_t)row * IN_DIM + kb + ch * 8);
        }
        {
            int row = tid >> 2;            // 0..127
            int ch  = tid & 3;
            cp_async16(sB + swz(row, ch), Bgb + (size_t)row * IN_DIM + kb + ch * 8);
        }
        cp_commit();
    };

    float acc[4][4][4];
#pragma unroll
    for (int mt = 0; mt < 4; mt++)
#pragma unroll
        for (int nt = 0; nt < 4; nt++)
#pragma unroll
            for (int r = 0; r < 4; r++) acc[mt][nt][r] = 0.0f;

    // ldmatrix lane address components
    const int g   = lane >> 3;           // 0..3
    const int lr8 = lane & 7;            // 0..7
    // A: rows m0 + (g&1)*8 + lr8, chunk 2ks + (g>>1)
    const int a_row_off = ((g & 1) << 3) + lr8;
    const int a_ch_off  = g >> 1;
    // B: rows n0 + (g>>1)*8 + lr8, chunk 2ks + (g&1)
    const int b_row_off = ((g >> 1) << 3) + lr8;
    const int b_ch_off  = g & 1;

    // prologue: fill stages 0..2
    load_stage(0, 0);
    load_stage(1, BK);
    load_stage(2, 2 * BK);

    for (int it = 0; it < NIT; ++it) {
        cp_wait<2>();
        __syncthreads();

        // prefetch stage it+3 (overwrites stage read at it-1; sync above protects)
        if (it + 3 < NIT) load_stage((it + 3) & 3, (it + 3) * BK);
        else cp_commit();   // keep group counts aligned

        const uint32_t sA = sbase + (it & 3) * STAGE;
        const uint32_t sB = sA + A_TILE;

#pragma unroll
        for (int ks = 0; ks < 2; ks++) {
            uint32_t af[4][4];
#pragma unroll
            for (int mt = 0; mt < 4; mt++) {
                const int row = warpm * 64 + mt * 16 + a_row_off;
                ldmatrix_x4(af[mt][0], af[mt][1], af[mt][2], af[mt][3],
                            sA + swz(row, 2 * ks + a_ch_off));
            }
            uint32_t bf[4][2];
#pragma unroll
            for (int bt = 0; bt < 2; bt++) {
                const int row = warpn * 32 + bt * 16 + b_row_off;
                ldmatrix_x4(bf[2 * bt][0], bf[2 * bt][1],
                            bf[2 * bt + 1][0], bf[2 * bt + 1][1],
                            sB + swz(row, 2 * ks + b_ch_off));
            }
#pragma unroll
            for (int mt = 0; mt < 4; mt++)
#pragma unroll
                for (int nt = 0; nt < 4; nt++)
                    mma_f16(acc[mt][nt][0], acc[mt][nt][1],
                            acc[mt][nt][2], acc[mt][nt][3],
                            af[mt][0], af[mt][1], af[mt][2], af[mt][3],
                            bf[nt][0], bf[nt][1]);
        }
    }

    // epilogue
    const int lr = lane >> 2;
    const int lk = lane & 3;
#pragma unroll
    for (int mt = 0; mt < 4; mt++) {
        const int r0 = brow + warpm * 64 + mt * 16 + lr;
#pragma unroll
        for (int nt = 0; nt < 4; nt++) {
            const int ccol = bcol + warpn * 32 + nt * 8 + 2 * lk;
            *(float2*)(C + (size_t)r0       * OUT_DIM + ccol) =
                make_float2(acc[mt][nt][0], acc[mt][nt][1]);
            *(float2*)(C + (size_t)(r0 + 8) * OUT_DIM + ccol) =
                make_float2(acc[mt][nt][2], acc[mt][nt][3]);
        }
    }
}

// ---------------------------------------------------------------------------
// Launch
// ---------------------------------------------------------------------------
extern "C" void kernel_launch(void* const* d_in, const int* in_sizes, int n_in,
                              void* d_out, int out_size)
{
    const float*  x       = (const float*) d_in[0];
    const int4*   codes   = (const int4*)  d_in[1];
    const float*  scalers = (const float*) d_in[2];
    const float*  Aw      = (const float*) d_in[3];
    const float*  Bw      = (const float*) d_in[4];
    float*        out     = (float*)d_out;

    // 1) W_eff fp16 (dequant + LoRA fold)
    dequant_fold_kernel<<<(OUT_DIM * IN_DIM / 4) / 256, 256>>>(codes, scalers, Aw, Bw);

    // 1b) x fp16
    x_to_half_kernel<<<((size_t)N_TOKENS * IN_DIM / 8) / 256, 256>>>((const float4*)x);

    // 2) fp16 mma GEMM
    {
        static bool attr_set = false;
        if (!attr_set) {
            cudaFuncSetAttribute(gemm_f16_kernel,
                                 cudaFuncAttributeMaxDynamicSharedMemorySize, SMEM_DYN);
            attr_set = true;
        }
        dim3 grid(OUT_DIM / BN, N_TOKENS / BM);   // (32, 32)
        gemm_f16_kernel<<<grid, 512, SMEM_DYN>>>(out);
    }
}

// round 6
// speedup vs baseline: 7.2719x; 1.0165x over previous
#include <cuda_runtime.h>
#include <cuda_fp16.h>
#include <stdint.h>

// ---------------------------------------------------------------------------
// Problem constants
// ---------------------------------------------------------------------------
static constexpr int IN_DIM   = 4096;   // K
static constexpr int OUT_DIM  = 4096;   // N
static constexpr int N_TOKENS = 8192;   // M
static constexpr int RANK     = 16;
static constexpr float LORA_SCALE = 2.0f;   // ALPHA / RANK

// GEMM tiling: CTA 128x256, 8 warps (2m x 4n), warp tile 64x64, BK=32 halves.
static constexpr int BM = 128;
static constexpr int BN = 256;
static constexpr int BK = 32;                       // halves (64 B rows)
static constexpr int NIT = IN_DIM / BK;             // 128
static constexpr int A_TILE = BM * BK * 2;          // 8 KB
static constexpr int B_TILE = BN * BK * 2;          // 16 KB
static constexpr int STAGE  = A_TILE + B_TILE;      // 24 KB
static constexpr int NSTAGE = 4;
static constexpr int SMEM_DYN = NSTAGE * STAGE;     // 96 KB

// NF4 codebook
__constant__ float c_nf4[16] = {
    -1.0f, -0.6961928009986877f, -0.5250730514526367f, -0.39491748809814453f,
    -0.28444138169288635f, -0.18477343022823334f, -0.09105003625154495f, 0.0f,
    0.07958029955625534f, 0.16093020141124725f, 0.24611230194568634f,
    0.33791524171829224f, 0.44070982933044434f, 0.5626170039176941f,
    0.7229568362236023f, 1.0f};

// fp16 scratch: W_eff (32 MB) and x (64 MB)
__device__ __half g_weffh[(size_t)OUT_DIM * IN_DIM];
__device__ __half g_xh[(size_t)N_TOKENS * IN_DIM];

// ---------------------------------------------------------------------------
// Helpers
// ---------------------------------------------------------------------------
__device__ __forceinline__ uint32_t smem_u32(const void* p) {
    uint32_t a;
    asm("{ .reg .u64 t; cvta.to.shared.u64 t, %1; cvt.u32.u64 %0, t; }"
        : "=r"(a) : "l"(p));
    return a;
}
__device__ __forceinline__ void cp_async16(uint32_t dst, const void* src) {
    asm volatile("cp.async.cg.shared.global [%0], [%1], 16;" :: "r"(dst), "l"(src));
}
__device__ __forceinline__ void cp_commit() {
    asm volatile("cp.async.commit_group;" ::: "memory");
}
template <int N>
__device__ __forceinline__ void cp_wait() {
    asm volatile("cp.async.wait_group %0;" :: "n"(N) : "memory");
}
__device__ __forceinline__ void ldmatrix_x4(uint32_t& r0, uint32_t& r1,
                                            uint32_t& r2, uint32_t& r3,
                                            uint32_t addr) {
    asm volatile("ldmatrix.sync.aligned.m8n8.x4.shared.b16 {%0,%1,%2,%3}, [%4];"
                 : "=r"(r0), "=r"(r1), "=r"(r2), "=r"(r3) : "r"(addr));
}
__device__ __forceinline__ void mma_f16(
    float& c0, float& c1, float& c2, float& c3,
    uint32_t a0, uint32_t a1, uint32_t a2, uint32_t a3,
    uint32_t b0, uint32_t b1)
{
    asm volatile(
        "mma.sync.aligned.m16n8k16.row.col.f32.f16.f16.f32 "
        "{%0,%1,%2,%3}, {%4,%5,%6,%7}, {%8,%9}, {%0,%1,%2,%3};"
        : "+f"(c0), "+f"(c1), "+f"(c2), "+f"(c3)
        : "r"(a0), "r"(a1), "r"(a2), "r"(a3), "r"(b0), "r"(b1));
}

// smem tile: row-major, 64 B rows, 4 chunks of 16 B, XOR-swizzled by (row>>1)&3
// -> conflict-free for ldmatrix 8-row groups (validated round 4).
__device__ __forceinline__ uint32_t swz(int row, int chunk) {
    return (uint32_t)(row * 64 + ((chunk ^ ((row >> 1) & 3)) << 4));
}

// ---------------------------------------------------------------------------
// Kernel 1: NF4 dequant + LoRA fold -> fp16 W_eff (8 elements / thread)
// ---------------------------------------------------------------------------
__global__ __launch_bounds__(256) void dequant_fold_kernel(
    const int4*  __restrict__ codes4,
    const float* __restrict__ scalers,
    const float* __restrict__ Aw,   // [RANK, IN_DIM]
    const float* __restrict__ Bw)   // [OUT_DIM, RANK]
{
    int t = blockIdx.x * 256 + threadIdx.x;
    int base = t * 8;                 // always inside one 64-elem scaler block
    int o = base >> 12;
    int i = base & (IN_DIM - 1);

    int4 c0 = codes4[t * 2 + 0];
    int4 c1 = codes4[t * 2 + 1];
    float sc = scalers[base >> 6];

    float w[8];
    w[0] = c_nf4[c0.x] * sc; w[1] = c_nf4[c0.y] * sc;
    w[2] = c_nf4[c0.z] * sc; w[3] = c_nf4[c0.w] * sc;
    w[4] = c_nf4[c1.x] * sc; w[5] = c_nf4[c1.y] * sc;
    w[6] = c_nf4[c1.z] * sc; w[7] = c_nf4[c1.w] * sc;

    float4 accA = make_float4(0.f, 0.f, 0.f, 0.f);
    float4 accB = make_float4(0.f, 0.f, 0.f, 0.f);
    const float* bw = Bw + (o << 4);
#pragma unroll
    for (int r = 0; r < RANK; r++) {
        float b = bw[r];
        float4 a0 = *(const float4*)(Aw + (r << 12) + i);
        float4 a1 = *(const float4*)(Aw + (r << 12) + i + 4);
        accA.x = fmaf(b, a0.x, accA.x);
        accA.y = fmaf(b, a0.y, accA.y);
        accA.z = fmaf(b, a0.z, accA.z);
        accA.w = fmaf(b, a0.w, accA.w);
        accB.x = fmaf(b, a1.x, accB.x);
        accB.y = fmaf(b, a1.y, accB.y);
        accB.z = fmaf(b, a1.z, accB.z);
        accB.w = fmaf(b, a1.w, accB.w);
    }
    __half2 h0 = __floats2half2_rn(fmaf(LORA_SCALE, accA.x, w[0]),
                                   fmaf(LORA_SCALE, accA.y, w[1]));
    __half2 h1 = __floats2half2_rn(fmaf(LORA_SCALE, accA.z, w[2]),
                                   fmaf(LORA_SCALE, accA.w, w[3]));
    __half2 h2 = __floats2half2_rn(fmaf(LORA_SCALE, accB.x, w[4]),
                                   fmaf(LORA_SCALE, accB.y, w[5]));
    __half2 h3 = __floats2half2_rn(fmaf(LORA_SCALE, accB.z, w[6]),
                                   fmaf(LORA_SCALE, accB.w, w[7]));
    uint4 packed;
    packed.x = *(uint32_t*)&h0;
    packed.y = *(uint32_t*)&h1;
    packed.z = *(uint32_t*)&h2;
    packed.w = *(uint32_t*)&h3;
    *(uint4*)(g_weffh + base) = packed;
}

// ---------------------------------------------------------------------------
// Kernel 1b: x -> fp16 (16 elements / thread)
// ---------------------------------------------------------------------------
__global__ __launch_bounds__(256) void x_to_half_kernel(const float4* __restrict__ x4)
{
    int idx = blockIdx.x * 256 + threadIdx.x;    // one per 16 elements
    uint4 p[2];
#pragma unroll
    for (int h = 0; h < 2; h++) {
        float4 v0 = x4[idx * 4 + h * 2 + 0];
        float4 v1 = x4[idx * 4 + h * 2 + 1];
        __half2 h0 = __floats2half2_rn(v0.x, v0.y);
        __half2 h1 = __floats2half2_rn(v0.z, v0.w);
        __half2 h2 = __floats2half2_rn(v1.x, v1.y);
        __half2 h3 = __floats2half2_rn(v1.z, v1.w);
        p[h].x = *(uint32_t*)&h0;
        p[h].y = *(uint32_t*)&h1;
        p[h].z = *(uint32_t*)&h2;
        p[h].w = *(uint32_t*)&h3;
    }
    *(uint4*)(g_xh + (size_t)idx * 16 + 0) = p[0];
    *(uint4*)(g_xh + (size_t)idx * 16 + 8) = p[1];
}

// ---------------------------------------------------------------------------
// Kernel 2: fp16 mma.sync GEMM  C[M,N] = A[M,K] * B[N,K]^T
// A = g_xh, B = g_weffh. 256 threads (8 warps, 2m x 4n), warp tile 64x64.
// ---------------------------------------------------------------------------
__global__ __launch_bounds__(256, 1)
void gemm_f16_kernel(float* __restrict__ C)
{
    extern __shared__ char dynb[];
    const uint32_t sbase = smem_u32(dynb);

    const int tid   = threadIdx.x;
    const int wid   = tid >> 5;
    const int lane  = tid & 31;
    const int warpm = wid & 1;           // 0..1 -> m offset *64
    const int warpn = wid >> 1;          // 0..3 -> n offset *64

    const int brow = blockIdx.y * BM;
    const int bcol = blockIdx.x * BN;

    const __half* Agb = g_xh    + (size_t)brow * IN_DIM;
    const __half* Bgb = g_weffh + (size_t)bcol * IN_DIM;

    // --- stage loader: A 512 chunks (2/thread), B 1024 chunks (4/thread) ---
    auto load_stage = [&](int stage, int kb) {
        const uint32_t sA = sbase + stage * STAGE;
        const uint32_t sB = sA + A_TILE;
#pragma unroll
        for (int i = 0; i < 2; i++) {
            int idx = tid + i * 256;
            int row = idx >> 2;            // 0..127
            int ch  = idx & 3;
            cp_async16(sA + swz(row, ch), Agb + (size_t)row * IN_DIM + kb + ch * 8);
        }
#pragma unroll
        for (int i = 0; i < 4; i++) {
            int idx = tid + i * 256;
            int row = idx >> 2;            // 0..255
            int ch  = idx & 3;
            cp_async16(sB + swz(row, ch), Bgb + (size_t)row * IN_DIM + kb + ch * 8);
        }
        cp_commit();
    };

    float acc[4][8][4];
#pragma unroll
    for (int mt = 0; mt < 4; mt++)
#pragma unroll
        for (int nt = 0; nt < 8; nt++)
#pragma unroll
            for (int r = 0; r < 4; r++) acc[mt][nt][r] = 0.0f;

    // ldmatrix lane address components
    const int g   = lane >> 3;           // 0..3
    const int lr8 = lane & 7;            // 0..7
    const int a_row_off = ((g & 1) << 3) + lr8;   // A: m16 x k16 tile
    const int a_ch_off  = g >> 1;
    const int b_row_off = ((g >> 1) << 3) + lr8;  // B: n16 x k16 tile
    const int b_ch_off  = g & 1;

    // prologue: fill stages 0..2
    load_stage(0, 0);
    load_stage(1, BK);
    load_stage(2, 2 * BK);

    for (int it = 0; it < NIT; ++it) {
        cp_wait<2>();
        __syncthreads();

        if (it + 3 < NIT) load_stage((it + 3) & 3, (it + 3) * BK);
        else cp_commit();   // keep group counts aligned

        const uint32_t sA = sbase + (it & 3) * STAGE;
        const uint32_t sB = sA + A_TILE;

#pragma unroll
        for (int ks = 0; ks < 2; ks++) {
            uint32_t af[4][4];
#pragma unroll
            for (int mt = 0; mt < 4; mt++) {
                const int row = warpm * 64 + mt * 16 + a_row_off;
                ldmatrix_x4(af[mt][0], af[mt][1], af[mt][2], af[mt][3],
                            sA + swz(row, 2 * ks + a_ch_off));
            }
            uint32_t bf[8][2];
#pragma unroll
            for (int bt = 0; bt < 4; bt++) {
                const int row = warpn * 64 + bt * 16 + b_row_off;
                ldmatrix_x4(bf[2 * bt][0], bf[2 * bt][1],
                            bf[2 * bt + 1][0], bf[2 * bt + 1][1],
                            sB + swz(row, 2 * ks + b_ch_off));
            }
#pragma unroll
            for (int mt = 0; mt < 4; mt++)
#pragma unroll
                for (int nt = 0; nt < 8; nt++)
                    mma_f16(acc[mt][nt][0], acc[mt][nt][1],
                            acc[mt][nt][2], acc[mt][nt][3],
                            af[mt][0], af[mt][1], af[mt][2], af[mt][3],
                            bf[nt][0], bf[nt][1]);
        }
    }

    // epilogue
    const int lr = lane >> 2;
    const int lk = lane & 3;
#pragma unroll
    for (int mt = 0; mt < 4; mt++) {
        const int r0 = brow + warpm * 64 + mt * 16 + lr;
#pragma unroll
        for (int nt = 0; nt < 8; nt++) {
            const int ccol = bcol + warpn * 64 + nt * 8 + 2 * lk;
            *(float2*)(C + (size_t)r0       * OUT_DIM + ccol) =
                make_float2(acc[mt][nt][0], acc[mt][nt][1]);
            *(float2*)(C + (size_t)(r0 + 8) * OUT_DIM + ccol) =
                make_float2(acc[mt][nt][2], acc[mt][nt][3]);
        }
    }
}

// ---------------------------------------------------------------------------
// Launch
// ---------------------------------------------------------------------------
extern "C" void kernel_launch(void* const* d_in, const int* in_sizes, int n_in,
                              void* d_out, int out_size)
{
    const float*  x       = (const float*) d_in[0];
    const int4*   codes   = (const int4*)  d_in[1];
    const float*  scalers = (const float*) d_in[2];
    const float*  Aw      = (const float*) d_in[3];
    const float*  Bw      = (const float*) d_in[4];
    float*        out     = (float*)d_out;

    // 1) W_eff fp16 (dequant + LoRA fold)
    dequant_fold_kernel<<<(OUT_DIM * IN_DIM / 8) / 256, 256>>>(codes, scalers, Aw, Bw);

    // 1b) x fp16
    x_to_half_kernel<<<((size_t)N_TOKENS * IN_DIM / 16) / 256, 256>>>((const float4*)x);

    // 2) fp16 mma GEMM
    {
        static bool attr_set = false;
        if (!attr_set) {
            cudaFuncSetAttribute(gemm_f16_kernel,
                                 cudaFuncAttributeMaxDynamicSharedMemorySize, SMEM_DYN);
            attr_set = true;
        }
        dim3 grid(OUT_DIM / BN, N_TOKENS / BM);   // (16, 64)
        gemm_f16_kernel<<<grid, 256, SMEM_DYN>>>(out);
    }
}

// round 7
// speedup vs baseline: 8.2978x; 1.1411x over previous
#include <cuda_runtime.h>
#include <cuda_fp16.h>
#include <stdint.h>

// ---------------------------------------------------------------------------
// Problem constants
// ---------------------------------------------------------------------------
static constexpr int IN_DIM   = 4096;   // K
static constexpr int OUT_DIM  = 4096;   // N
static constexpr int N_TOKENS = 8192;   // M
static constexpr int RANK     = 16;
static constexpr float LORA_SCALE = 2.0f;   // ALPHA / RANK

// GEMM tiling: CTA 128x128, 8 warps (2m x 4n), warp tile 64x32, BK=32 halves.
// 2 CTAs/SM (regs <=128, smem 48KB/CTA).
static constexpr int BM = 128;
static constexpr int BN = 128;
static constexpr int BK = 32;                       // halves (64 B rows)
static constexpr int NIT = IN_DIM / BK;             // 128
static constexpr int A_TILE = BM * BK * 2;          // 8 KB
static constexpr int B_TILE = BN * BK * 2;          // 8 KB
static constexpr int STAGE  = A_TILE + B_TILE;      // 16 KB
static constexpr int NSTAGE = 3;
static constexpr int SMEM_DYN = NSTAGE * STAGE;     // 48 KB

// dequant tiling
static constexpr int OB = 16;     // o-rows per block
static constexpr int IB = 1024;   // i-cols per block
static constexpr int DQ_SMEM = RANK * IB * 4;       // 64 KB (A slice)

// NF4 codebook
__constant__ float c_nf4[16] = {
    -1.0f, -0.6961928009986877f, -0.5250730514526367f, -0.39491748809814453f,
    -0.28444138169288635f, -0.18477343022823334f, -0.09105003625154495f, 0.0f,
    0.07958029955625534f, 0.16093020141124725f, 0.24611230194568634f,
    0.33791524171829224f, 0.44070982933044434f, 0.5626170039176941f,
    0.7229568362236023f, 1.0f};

// fp16 scratch: W_eff (32 MB) and x (64 MB)
__device__ __half g_weffh[(size_t)OUT_DIM * IN_DIM];
__device__ __half g_xh[(size_t)N_TOKENS * IN_DIM];

// ---------------------------------------------------------------------------
// Helpers
// ---------------------------------------------------------------------------
__device__ __forceinline__ uint32_t smem_u32(const void* p) {
    uint32_t a;
    asm("{ .reg .u64 t; cvta.to.shared.u64 t, %1; cvt.u32.u64 %0, t; }"
        : "=r"(a) : "l"(p));
    return a;
}
__device__ __forceinline__ void cp_async16(uint32_t dst, const void* src) {
    asm volatile("cp.async.cg.shared.global [%0], [%1], 16;" :: "r"(dst), "l"(src));
}
__device__ __forceinline__ void cp_commit() {
    asm volatile("cp.async.commit_group;" ::: "memory");
}
template <int N>
__device__ __forceinline__ void cp_wait() {
    asm volatile("cp.async.wait_group %0;" :: "n"(N) : "memory");
}
__device__ __forceinline__ void ldmatrix_x4(uint32_t& r0, uint32_t& r1,
                                            uint32_t& r2, uint32_t& r3,
                                            uint32_t addr) {
    asm volatile("ldmatrix.sync.aligned.m8n8.x4.shared.b16 {%0,%1,%2,%3}, [%4];"
                 : "=r"(r0), "=r"(r1), "=r"(r2), "=r"(r3) : "r"(addr));
}
__device__ __forceinline__ void mma_f16(
    float& c0, float& c1, float& c2, float& c3,
    uint32_t a0, uint32_t a1, uint32_t a2, uint32_t a3,
    uint32_t b0, uint32_t b1)
{
    asm volatile(
        "mma.sync.aligned.m16n8k16.row.col.f32.f16.f16.f32 "
        "{%0,%1,%2,%3}, {%4,%5,%6,%7}, {%8,%9}, {%0,%1,%2,%3};"
        : "+f"(c0), "+f"(c1), "+f"(c2), "+f"(c3)
        : "r"(a0), "r"(a1), "r"(a2), "r"(a3), "r"(b0), "r"(b1));
}

// smem tile: row-major, 64 B rows, 4 chunks of 16 B, XOR-swizzled by (row>>1)&3
// -> conflict-free for ldmatrix 8-row groups (validated rounds 4-6).
__device__ __forceinline__ uint32_t swz(int row, int chunk) {
    return (uint32_t)(row * 64 + ((chunk ^ ((row >> 1) & 3)) << 4));
}

// ---------------------------------------------------------------------------
// Kernel 1: NF4 dequant + LoRA fold -> fp16 W_eff, smem-tiled A reuse.
// Block: 16 o-rows x 1024 i-cols. A slice [16 x 1024] cached in smem (64 KB).
// Thread: o_local = tid&15, i_group = tid>>4 -> 64 consecutive i (one scaler).
// ---------------------------------------------------------------------------
__global__ __launch_bounds__(256) void dequant_fold_kernel(
    const int4*  __restrict__ codes4,
    const float* __restrict__ scalers,
    const float* __restrict__ Aw,   // [RANK, IN_DIM]
    const float* __restrict__ Bw)   // [OUT_DIM, RANK]
{
    extern __shared__ float As[];             // [RANK][IB]
    float4* As4 = (float4*)As;                // [RANK][IB/4]

    const int tid = threadIdx.x;
    const int i0  = blockIdx.x * IB;
    const int o0  = blockIdx.y * OB;

    // cooperative A-slice load: RANK*IB/4 = 4096 float4, 16 per thread
    const float4* Aw4 = (const float4*)Aw;
#pragma unroll
    for (int j = 0; j < (RANK * IB / 4) / 256; j++) {
        int idx4 = tid + j * 256;
        int r    = idx4 >> 8;                 // /(IB/4)
        int c4   = idx4 & 255;
        As4[r * (IB / 4) + c4] = Aw4[r * (IN_DIM / 4) + (i0 >> 2) + c4];
    }

    // B row for this thread's o into registers
    const int o_local = tid & 15;
    const int ig      = tid >> 4;
    const int o       = o0 + o_local;
    float breg[RANK];
    {
        const float4* Bw4 = (const float4*)(Bw + (o << 4));
#pragma unroll
        for (int f = 0; f < 4; f++) {
            float4 v = Bw4[f];
            breg[f * 4 + 0] = v.x; breg[f * 4 + 1] = v.y;
            breg[f * 4 + 2] = v.z; breg[f * 4 + 3] = v.w;
        }
    }
    __syncthreads();

    const size_t base = (size_t)o * IN_DIM + i0 + ig * 64;
    const float sc = scalers[base >> 6];

#pragma unroll
    for (int c = 0; c < 4; c++) {             // 4 chunks x 16 elems
        // LoRA partial: acc[j] over 16 elements
        float4 acc[4];
#pragma unroll
        for (int j = 0; j < 4; j++) acc[j] = make_float4(0.f, 0.f, 0.f, 0.f);
#pragma unroll
        for (int r = 0; r < RANK; r++) {
            float b = breg[r];
            const float4* ar = As4 + r * (IB / 4) + ig * 16 + c * 4;
#pragma unroll
            for (int j = 0; j < 4; j++) {
                float4 a = ar[j];
                acc[j].x = fmaf(b, a.x, acc[j].x);
                acc[j].y = fmaf(b, a.y, acc[j].y);
                acc[j].z = fmaf(b, a.z, acc[j].z);
                acc[j].w = fmaf(b, a.w, acc[j].w);
            }
        }
        // codes + combine
        uint4 packed[2];
#pragma unroll
        for (int j = 0; j < 4; j++) {
            int4 cd = codes4[(base >> 2) + c * 4 + j];
            float w0 = c_nf4[cd.x] * sc;
            float w1 = c_nf4[cd.y] * sc;
            float w2 = c_nf4[cd.z] * sc;
            float w3 = c_nf4[cd.w] * sc;
            __half2 h0 = __floats2half2_rn(fmaf(LORA_SCALE, acc[j].x, w0),
                                           fmaf(LORA_SCALE, acc[j].y, w1));
            __half2 h1 = __floats2half2_rn(fmaf(LORA_SCALE, acc[j].z, w2),
                                           fmaf(LORA_SCALE, acc[j].w, w3));
            ((uint32_t*)packed)[j * 2 + 0] = *(uint32_t*)&h0;
            ((uint32_t*)packed)[j * 2 + 1] = *(uint32_t*)&h1;
        }
        *(uint4*)(g_weffh + base + c * 16 + 0) = packed[0];
        *(uint4*)(g_weffh + base + c * 16 + 8) = packed[1];
    }
}

// ---------------------------------------------------------------------------
// Kernel 1b: x -> fp16 (16 elements / thread)
// ---------------------------------------------------------------------------
__global__ __launch_bounds__(256) void x_to_half_kernel(const float4* __restrict__ x4)
{
    int idx = blockIdx.x * 256 + threadIdx.x;    // one per 16 elements
    uint4 p[2];
#pragma unroll
    for (int h = 0; h < 2; h++) {
        float4 v0 = x4[idx * 4 + h * 2 + 0];
        float4 v1 = x4[idx * 4 + h * 2 + 1];
        __half2 h0 = __floats2half2_rn(v0.x, v0.y);
        __half2 h1 = __floats2half2_rn(v0.z, v0.w);
        __half2 h2 = __floats2half2_rn(v1.x, v1.y);
        __half2 h3 = __floats2half2_rn(v1.z, v1.w);
        p[h].x = *(uint32_t*)&h0;
        p[h].y = *(uint32_t*)&h1;
        p[h].z = *(uint32_t*)&h2;
        p[h].w = *(uint32_t*)&h3;
    }
    *(uint4*)(g_xh + (size_t)idx * 16 + 0) = p[0];
    *(uint4*)(g_xh + (size_t)idx * 16 + 8) = p[1];
}

// ---------------------------------------------------------------------------
// Kernel 2: fp16 mma.sync GEMM  C[M,N] = A[M,K] * B[N,K]^T
// A = g_xh, B = g_weffh. CTA 128x128, 8 warps (2m x 4n), warp tile 64x32.
// 3-stage cp.async, 2 CTAs/SM.
// ---------------------------------------------------------------------------
__global__ __launch_bounds__(256, 2)
void gemm_f16_kernel(float* __restrict__ C)
{
    extern __shared__ char dynb[];
    const uint32_t sbase = smem_u32(dynb);

    const int tid   = threadIdx.x;
    const int wid   = tid >> 5;
    const int lane  = tid & 31;
    const int warpm = wid & 1;           // 0..1 -> m offset *64
    const int warpn = wid >> 1;          // 0..3 -> n offset *32

    const int brow = blockIdx.y * BM;
    const int bcol = blockIdx.x * BN;

    const __half* Agb = g_xh    + (size_t)brow * IN_DIM;
    const __half* Bgb = g_weffh + (size_t)bcol * IN_DIM;

    // --- stage loader: A 512 chunks (2/thread), B 512 chunks (2/thread) ---
    auto load_stage = [&](int stage, int kb) {
        const uint32_t sA = sbase + stage * STAGE;
        const uint32_t sB = sA + A_TILE;
#pragma unroll
        for (int i = 0; i < 2; i++) {
            int idx = tid + i * 256;
            int row = idx >> 2;            // 0..127
            int ch  = idx & 3;
            cp_async16(sA + swz(row, ch), Agb + (size_t)row * IN_DIM + kb + ch * 8);
        }
#pragma unroll
        for (int i = 0; i < 2; i++) {
            int idx = tid + i * 256;
            int row = idx >> 2;            // 0..127
            int ch  = idx & 3;
            cp_async16(sB + swz(row, ch), Bgb + (size_t)row * IN_DIM + kb + ch * 8);
        }
        cp_commit();
    };

    float acc[4][4][4];
#pragma unroll
    for (int mt = 0; mt < 4; mt++)
#pragma unroll
        for (int nt = 0; nt < 4; nt++)
#pragma unroll
            for (int r = 0; r < 4; r++) acc[mt][nt][r] = 0.0f;

    // ldmatrix lane address components
    const int g   = lane >> 3;           // 0..3
    const int lr8 = lane & 7;            // 0..7
    const int a_row_off = ((g & 1) << 3) + lr8;   // A: m16 x k16 tile
    const int a_ch_off  = g >> 1;
    const int b_row_off = ((g >> 1) << 3) + lr8;  // B: n16 x k16 tile
    const int b_ch_off  = g & 1;

    // prologue: fill stages 0,1
    load_stage(0, 0);
    load_stage(1, BK);

    int s_cur = 0;   // stage for compute at iter it
    int s_pre = 2;   // stage to prefetch (it+2)

    for (int it = 0; it < NIT; ++it) {
        cp_wait<1>();
        __syncthreads();

        if (it + 2 < NIT) load_stage(s_pre, (it + 2) * BK);
        else cp_commit();   // keep one group per iter for wait<1> accounting

        const uint32_t sA = sbase + s_cur * STAGE;
        const uint32_t sB = sA + A_TILE;

#pragma unroll
        for (int ks = 0; ks < 2; ks++) {
            uint32_t af[4][4];
#pragma unroll
            for (int mt = 0; mt < 4; mt++) {
                const int row = warpm * 64 + mt * 16 + a_row_off;
                ldmatrix_x4(af[mt][0], af[mt][1], af[mt][2], af[mt][3],
                            sA + swz(row, 2 * ks + a_ch_off));
            }
            uint32_t bf[4][2];
#pragma unroll
            for (int bt = 0; bt < 2; bt++) {
                const int row = warpn * 32 + bt * 16 + b_row_off;
                ldmatrix_x4(bf[2 * bt][0], bf[2 * bt][1],
                            bf[2 * bt + 1][0], bf[2 * bt + 1][1],
                            sB + swz(row, 2 * ks + b_ch_off));
            }
#pragma unroll
            for (int mt = 0; mt < 4; mt++)
#pragma unroll
                for (int nt = 0; nt < 4; nt++)
                    mma_f16(acc[mt][nt][0], acc[mt][nt][1],
                            acc[mt][nt][2], acc[mt][nt][3],
                            af[mt][0], af[mt][1], af[mt][2], af[mt][3],
                            bf[nt][0], bf[nt][1]);
        }

        s_cur = (s_cur == 2) ? 0 : s_cur + 1;
        s_pre = (s_pre == 2) ? 0 : s_pre + 1;
    }

    // epilogue
    const int lr = lane >> 2;
    const int lk = lane & 3;
#pragma unroll
    for (int mt = 0; mt < 4; mt++) {
        const int r0 = brow + warpm * 64 + mt * 16 + lr;
#pragma unroll
        for (int nt = 0; nt < 4; nt++) {
            const int ccol = bcol + warpn * 32 + nt * 8 + 2 * lk;
            *(float2*)(C + (size_t)r0       * OUT_DIM + ccol) =
                make_float2(acc[mt][nt][0], acc[mt][nt][1]);
            *(float2*)(C + (size_t)(r0 + 8) * OUT_DIM + ccol) =
                make_float2(acc[mt][nt][2], acc[mt][nt][3]);
        }
    }
}

// ---------------------------------------------------------------------------
// Launch
// ---------------------------------------------------------------------------
extern "C" void kernel_launch(void* const* d_in, const int* in_sizes, int n_in,
                              void* d_out, int out_size)
{
    const float*  x       = (const float*) d_in[0];
    const int4*   codes   = (const int4*)  d_in[1];
    const float*  scalers = (const float*) d_in[2];
    const float*  Aw      = (const float*) d_in[3];
    const float*  Bw      = (const float*) d_in[4];
    float*        out     = (float*)d_out;

    static bool attr_set = false;
    if (!attr_set) {
        cudaFuncSetAttribute(gemm_f16_kernel,
                             cudaFuncAttributeMaxDynamicSharedMemorySize, SMEM_DYN);
        cudaFuncSetAttribute(dequant_fold_kernel,
                             cudaFuncAttributeMaxDynamicSharedMemorySize, DQ_SMEM);
        attr_set = true;
    }

    // 1) W_eff fp16 (dequant + LoRA fold), A-slice cached in smem
    {
        dim3 grid(IN_DIM / IB, OUT_DIM / OB);   // (4, 256)
        dequant_fold_kernel<<<grid, 256, DQ_SMEM>>>(codes, scalers, Aw, Bw);
    }

    // 1b) x fp16
    x_to_half_kernel<<<((size_t)N_TOKENS * IN_DIM / 16) / 256, 256>>>((const float4*)x);

    // 2) fp16 mma GEMM, 2 CTAs/SM
    {
        dim3 grid(OUT_DIM / BN, N_TOKENS / BM);   // (32, 64)
        gemm_f16_kernel<<<grid, 256, SMEM_DYN>>>(out);
    }
}

// round 8
// speedup vs baseline: 9.0458x; 1.0901x over previous
#include <cuda_runtime.h>
#include <cuda_fp16.h>
#include <stdint.h>

// ---------------------------------------------------------------------------
// Problem constants
// ---------------------------------------------------------------------------
static constexpr int IN_DIM   = 4096;   // K
static constexpr int OUT_DIM  = 4096;   // N
static constexpr int N_TOKENS = 8192;   // M
static constexpr int RANK     = 16;
static constexpr float LORA_SCALE = 2.0f;   // ALPHA / RANK

// GEMM tiling: CTA 128x128, 8 warps (2m x 4n), warp tile 64x32, BK=64 halves.
// 2 CTAs/SM (regs <=128, smem 96KB/CTA).
static constexpr int BM = 128;
static constexpr int BN = 128;
static constexpr int BK = 64;                       // halves (128 B rows)
static constexpr int NIT = IN_DIM / BK;             // 64
static constexpr int A_TILE = BM * BK * 2;          // 16 KB
static constexpr int B_TILE = BN * BK * 2;          // 16 KB
static constexpr int STAGE  = A_TILE + B_TILE;      // 32 KB
static constexpr int NSTAGE = 3;
static constexpr int SMEM_DYN = NSTAGE * STAGE;     // 96 KB

// dequant tiling
static constexpr int OB = 16;     // o-rows per block
static constexpr int IB = 512;    // i-cols per block
static constexpr int DQ_SMEM = RANK * IB * 4;       // 32 KB (A slice)

// NF4 codebook
__constant__ float c_nf4[16] = {
    -1.0f, -0.6961928009986877f, -0.5250730514526367f, -0.39491748809814453f,
    -0.28444138169288635f, -0.18477343022823334f, -0.09105003625154495f, 0.0f,
    0.07958029955625534f, 0.16093020141124725f, 0.24611230194568634f,
    0.33791524171829224f, 0.44070982933044434f, 0.5626170039176941f,
    0.7229568362236023f, 1.0f};

// fp16 scratch: W_eff (32 MB) and x (64 MB)
__device__ __half g_weffh[(size_t)OUT_DIM * IN_DIM];
__device__ __half g_xh[(size_t)N_TOKENS * IN_DIM];

// ---------------------------------------------------------------------------
// Helpers
// ---------------------------------------------------------------------------
__device__ __forceinline__ uint32_t smem_u32(const void* p) {
    uint32_t a;
    asm("{ .reg .u64 t; cvta.to.shared.u64 t, %1; cvt.u32.u64 %0, t; }"
        : "=r"(a) : "l"(p));
    return a;
}
__device__ __forceinline__ void cp_async16(uint32_t dst, const void* src) {
    asm volatile("cp.async.cg.shared.global [%0], [%1], 16;" :: "r"(dst), "l"(src));
}
__device__ __forceinline__ void cp_commit() {
    asm volatile("cp.async.commit_group;" ::: "memory");
}
template <int N>
__device__ __forceinline__ void cp_wait() {
    asm volatile("cp.async.wait_group %0;" :: "n"(N) : "memory");
}
__device__ __forceinline__ void ldmatrix_x4(uint32_t& r0, uint32_t& r1,
                                            uint32_t& r2, uint32_t& r3,
                                            uint32_t addr) {
    asm volatile("ldmatrix.sync.aligned.m8n8.x4.shared.b16 {%0,%1,%2,%3}, [%4];"
                 : "=r"(r0), "=r"(r1), "=r"(r2), "=r"(r3) : "r"(addr));
}
__device__ __forceinline__ void mma_f16(
    float& c0, float& c1, float& c2, float& c3,
    uint32_t a0, uint32_t a1, uint32_t a2, uint32_t a3,
    uint32_t b0, uint32_t b1)
{
    asm volatile(
        "mma.sync.aligned.m16n8k16.row.col.f32.f16.f16.f32 "
        "{%0,%1,%2,%3}, {%4,%5,%6,%7}, {%8,%9}, {%0,%1,%2,%3};"
        : "+f"(c0), "+f"(c1), "+f"(c2), "+f"(c3)
        : "r"(a0), "r"(a1), "r"(a2), "r"(a3), "r"(b0), "r"(b1));
}

// smem tile: row-major, 128 B rows, 8 chunks of 16 B, XOR-swizzled by (row&7).
// ldmatrix reads 8 rows at one chunk: swizzled chunks = c^0..c^7 -> all 8
// distinct 16B banks -> conflict-free.
__device__ __forceinline__ uint32_t swz(int row, int chunk) {
    return (uint32_t)(row * 128 + ((chunk ^ (row & 7)) << 4));
}

// ---------------------------------------------------------------------------
// Kernel 1: NF4 dequant + LoRA fold -> fp16 W_eff, smem-tiled A reuse.
// Block: 16 o-rows x 512 i-cols. A slice [16 x 512] cached in smem (32 KB).
// Thread: o_local = tid&15, ig = tid>>4 -> 32 consecutive i (within one scaler).
// ---------------------------------------------------------------------------
__global__ __launch_bounds__(256) void dequant_fold_kernel(
    const int4*  __restrict__ codes4,
    const float* __restrict__ scalers,
    const float* __restrict__ Aw,   // [RANK, IN_DIM]
    const float* __restrict__ Bw)   // [OUT_DIM, RANK]
{
    extern __shared__ float As[];             // [RANK][IB]
    float4* As4 = (float4*)As;                // [RANK][IB/4]

    const int tid = threadIdx.x;
    const int i0  = blockIdx.x * IB;
    const int o0  = blockIdx.y * OB;

    // cooperative A-slice load: RANK*IB/4 = 2048 float4, 8 per thread
    const float4* Aw4 = (const float4*)Aw;
#pragma unroll
    for (int j = 0; j < (RANK * IB / 4) / 256; j++) {
        int idx4 = tid + j * 256;
        int r    = idx4 >> 7;                 // /(IB/4)
        int c4   = idx4 & 127;
        As4[r * (IB / 4) + c4] = Aw4[r * (IN_DIM / 4) + (i0 >> 2) + c4];
    }

    // B row for this thread's o into registers
    const int o_local = tid & 15;
    const int ig      = tid >> 4;
    const int o       = o0 + o_local;
    float breg[RANK];
    {
        const float4* Bw4 = (const float4*)(Bw + (o << 4));
#pragma unroll
        for (int f = 0; f < 4; f++) {
            float4 v = Bw4[f];
            breg[f * 4 + 0] = v.x; breg[f * 4 + 1] = v.y;
            breg[f * 4 + 2] = v.z; breg[f * 4 + 3] = v.w;
        }
    }
    __syncthreads();

    const size_t base = (size_t)o * IN_DIM + i0 + ig * 32;
    const float sc = scalers[base >> 6];

#pragma unroll
    for (int c = 0; c < 2; c++) {             // 2 chunks x 16 elems
        float4 acc[4];
#pragma unroll
        for (int j = 0; j < 4; j++) acc[j] = make_float4(0.f, 0.f, 0.f, 0.f);
#pragma unroll
        for (int r = 0; r < RANK; r++) {
            float b = breg[r];
            const float4* ar = As4 + r * (IB / 4) + ig * 8 + c * 4;
#pragma unroll
            for (int j = 0; j < 4; j++) {
                float4 a = ar[j];
                acc[j].x = fmaf(b, a.x, acc[j].x);
                acc[j].y = fmaf(b, a.y, acc[j].y);
                acc[j].z = fmaf(b, a.z, acc[j].z);
                acc[j].w = fmaf(b, a.w, acc[j].w);
            }
        }
        uint4 packed[2];
#pragma unroll
        for (int j = 0; j < 4; j++) {
            int4 cd = codes4[(base >> 2) + c * 4 + j];
            float w0 = c_nf4[cd.x] * sc;
            float w1 = c_nf4[cd.y] * sc;
            float w2 = c_nf4[cd.z] * sc;
            float w3 = c_nf4[cd.w] * sc;
            __half2 h0 = __floats2half2_rn(fmaf(LORA_SCALE, acc[j].x, w0),
                                           fmaf(LORA_SCALE, acc[j].y, w1));
            __half2 h1 = __floats2half2_rn(fmaf(LORA_SCALE, acc[j].z, w2),
                                           fmaf(LORA_SCALE, acc[j].w, w3));
            ((uint32_t*)packed)[j * 2 + 0] = *(uint32_t*)&h0;
            ((uint32_t*)packed)[j * 2 + 1] = *(uint32_t*)&h1;
        }
        *(uint4*)(g_weffh + base + c * 16 + 0) = packed[0];
        *(uint4*)(g_weffh + base + c * 16 + 8) = packed[1];
    }
}

// ---------------------------------------------------------------------------
// Kernel 1b: x -> fp16 (16 elements / thread)
// ---------------------------------------------------------------------------
__global__ __launch_bounds__(256) void x_to_half_kernel(const float4* __restrict__ x4)
{
    int idx = blockIdx.x * 256 + threadIdx.x;
    uint4 p[2];
#pragma unroll
    for (int h = 0; h < 2; h++) {
        float4 v0 = x4[idx * 4 + h * 2 + 0];
        float4 v1 = x4[idx * 4 + h * 2 + 1];
        __half2 h0 = __floats2half2_rn(v0.x, v0.y);
        __half2 h1 = __floats2half2_rn(v0.z, v0.w);
        __half2 h2 = __floats2half2_rn(v1.x, v1.y);
        __half2 h3 = __floats2half2_rn(v1.z, v1.w);
        p[h].x = *(uint32_t*)&h0;
        p[h].y = *(uint32_t*)&h1;
        p[h].z = *(uint32_t*)&h2;
        p[h].w = *(uint32_t*)&h3;
    }
    *(uint4*)(g_xh + (size_t)idx * 16 + 0) = p[0];
    *(uint4*)(g_xh + (size_t)idx * 16 + 8) = p[1];
}

// ---------------------------------------------------------------------------
// Kernel 2: fp16 mma.sync GEMM  C[M,N] = A[M,K] * B[N,K]^T
// A = g_xh, B = g_weffh. CTA 128x128, 8 warps (2m x 4n), warp tile 64x32.
// BK=64, 3-stage cp.async, 2 CTAs/SM.
// ---------------------------------------------------------------------------
__global__ __launch_bounds__(256, 2)
void gemm_f16_kernel(float* __restrict__ C)
{
    extern __shared__ char dynb[];
    const uint32_t sbase = smem_u32(dynb);

    const int tid   = threadIdx.x;
    const int wid   = tid >> 5;
    const int lane  = tid & 31;
    const int warpm = wid & 1;           // 0..1 -> m offset *64
    const int warpn = wid >> 1;          // 0..3 -> n offset *32

    const int brow = blockIdx.y * BM;
    const int bcol = blockIdx.x * BN;

    const __half* Agb = g_xh    + (size_t)brow * IN_DIM;
    const __half* Bgb = g_weffh + (size_t)bcol * IN_DIM;

    // --- stage loader: A 1024 chunks (4/thread), B 1024 chunks (4/thread) ---
    auto load_stage = [&](int stage, int kb) {
        const uint32_t sA = sbase + stage * STAGE;
        const uint32_t sB = sA + A_TILE;
#pragma unroll
        for (int i = 0; i < 4; i++) {
            int idx = tid + i * 256;
            int row = idx >> 3;            // 0..127
            int ch  = idx & 7;
            cp_async16(sA + swz(row, ch), Agb + (size_t)row * IN_DIM + kb + ch * 8);
        }
#pragma unroll
        for (int i = 0; i < 4; i++) {
            int idx = tid + i * 256;
            int row = idx >> 3;            // 0..127
            int ch  = idx & 7;
            cp_async16(sB + swz(row, ch), Bgb + (size_t)row * IN_DIM + kb + ch * 8);
        }
        cp_commit();
    };

    float acc[4][4][4];
#pragma unroll
    for (int mt = 0; mt < 4; mt++)
#pragma unroll
        for (int nt = 0; nt < 4; nt++)
#pragma unroll
            for (int r = 0; r < 4; r++) acc[mt][nt][r] = 0.0f;

    // ldmatrix lane address components
    const int g   = lane >> 3;           // 0..3
    const int lr8 = lane & 7;            // 0..7
    const int a_row_off = ((g & 1) << 3) + lr8;   // A: m16 x k16 tile
    const int a_ch_off  = g >> 1;
    const int b_row_off = ((g >> 1) << 3) + lr8;  // B: n16 x k16 tile
    const int b_ch_off  = g & 1;

    // prologue: fill stages 0,1
    load_stage(0, 0);
    load_stage(1, BK);

    int s_cur = 0;
    int s_pre = 2;

    for (int it = 0; it < NIT; ++it) {
        cp_wait<1>();
        __syncthreads();

        if (it + 2 < NIT) load_stage(s_pre, (it + 2) * BK);
        else cp_commit();   // keep one group per iter for wait<1> accounting

        const uint32_t sA = sbase + s_cur * STAGE;
        const uint32_t sB = sA + A_TILE;

#pragma unroll
        for (int ks = 0; ks < 4; ks++) {
            uint32_t af[4][4];
#pragma unroll
            for (int mt = 0; mt < 4; mt++) {
                const int row = warpm * 64 + mt * 16 + a_row_off;
                ldmatrix_x4(af[mt][0], af[mt][1], af[mt][2], af[mt][3],
                            sA + swz(row, 2 * ks + a_ch_off));
            }
            uint32_t bf[4][2];
#pragma unroll
            for (int bt = 0; bt < 2; bt++) {
                const int row = warpn * 32 + bt * 16 + b_row_off;
                ldmatrix_x4(bf[2 * bt][0], bf[2 * bt][1],
                            bf[2 * bt + 1][0], bf[2 * bt + 1][1],
                            sB + swz(row, 2 * ks + b_ch_off));
            }
#pragma unroll
            for (int mt = 0; mt < 4; mt++)
#pragma unroll
                for (int nt = 0; nt < 4; nt++)
                    mma_f16(acc[mt][nt][0], acc[mt][nt][1],
                            acc[mt][nt][2], acc[mt][nt][3],
                            af[mt][0], af[mt][1], af[mt][2], af[mt][3],
                            bf[nt][0], bf[nt][1]);
        }

        s_cur = (s_cur == 2) ? 0 : s_cur + 1;
        s_pre = (s_pre == 2) ? 0 : s_pre + 1;
    }

    // epilogue
    const int lr = lane >> 2;
    const int lk = lane & 3;
#pragma unroll
    for (int mt = 0; mt < 4; mt++) {
        const int r0 = brow + warpm * 64 + mt * 16 + lr;
#pragma unroll
        for (int nt = 0; nt < 4; nt++) {
            const int ccol = bcol + warpn * 32 + nt * 8 + 2 * lk;
            *(float2*)(C + (size_t)r0       * OUT_DIM + ccol) =
                make_float2(acc[mt][nt][0], acc[mt][nt][1]);
            *(float2*)(C + (size_t)(r0 + 8) * OUT_DIM + ccol) =
                make_float2(acc[mt][nt][2], acc[mt][nt][3]);
        }
    }
}

// ---------------------------------------------------------------------------
// Launch
// ---------------------------------------------------------------------------
extern "C" void kernel_launch(void* const* d_in, const int* in_sizes, int n_in,
                              void* d_out, int out_size)
{
    const float*  x       = (const float*) d_in[0];
    const int4*   codes   = (const int4*)  d_in[1];
    const float*  scalers = (const float*) d_in[2];
    const float*  Aw      = (const float*) d_in[3];
    const float*  Bw      = (const float*) d_in[4];
    float*        out     = (float*)d_out;

    static bool attr_set = false;
    if (!attr_set) {
        cudaFuncSetAttribute(gemm_f16_kernel,
                             cudaFuncAttributeMaxDynamicSharedMemorySize, SMEM_DYN);
        cudaFuncSetAttribute(dequant_fold_kernel,
                             cudaFuncAttributeMaxDynamicSharedMemorySize, DQ_SMEM);
        attr_set = true;
    }

    // 1) W_eff fp16 (dequant + LoRA fold), A-slice cached in smem
    {
        dim3 grid(IN_DIM / IB, OUT_DIM / OB);   // (8, 256)
        dequant_fold_kernel<<<grid, 256, DQ_SMEM>>>(codes, scalers, Aw, Bw);
    }

    // 1b) x fp16
    x_to_half_kernel<<<((size_t)N_TOKENS * IN_DIM / 16) / 256, 256>>>((const float4*)x);

    // 2) fp16 mma GEMM, 2 CTAs/SM
    {
        dim3 grid(OUT_DIM / BN, N_TOKENS / BM);   // (32, 64)
        gemm_f16_kernel<<<grid, 256, SMEM_DYN>>>(out);
    }
}